// round 16
// baseline (speedup 1.0000x reference)
#include <cuda_runtime.h>
#include <cstdint>
#include <cstddef>

#define BATCHN 10
#define HID    128
#define OUTD   7
#define TLEN   2048
#define TPB    256      // 2 CTAs per batch; thread = one full gate row (ty,k)
#define KPC    64       // hidden units owned per CTA
#define PSTR   68       // plog row stride (floats): 64 partials + 4 pad; 272B, 16B-aligned,
                        // consumer banks 4*o apart (conflict-free), producer 16 lanes distinct

typedef unsigned long long ull;

__device__ __forceinline__ uint32_t sm2u(const void* p) {
    return (uint32_t)__cvta_generic_to_shared(const_cast<void*>(p));
}
__device__ __forceinline__ uint32_t ctarank() {
    uint32_t r; asm("mov.u32 %0, %%cluster_ctarank;" : "=r"(r)); return r;
}
__device__ __forceinline__ void dst_f32(uint32_t saddr, uint32_t rk, float v) {
    uint32_t ra;
    asm volatile("mapa.shared::cluster.u32 %0, %1, %2;" : "=r"(ra) : "r"(saddr), "r"(rk));
    asm volatile("st.shared::cluster.f32 [%0], %1;" :: "r"(ra), "f"(v) : "memory");
}
__device__ __forceinline__ ull fma2(ull a, ull b, ull c) {
    ull d; asm("fma.rn.f32x2 %0, %1, %2, %3;" : "=l"(d) : "l"(a), "l"(b), "l"(c)); return d;
}
__device__ __forceinline__ ull pk2(float lo, float hi) {
    ull r; asm("mov.b64 %0, {%1, %2};" : "=l"(r) : "f"(lo), "f"(hi)); return r;
}
__device__ __forceinline__ float2 unpk2(ull v) {
    float2 f; asm("mov.b64 {%0, %1}, %2;" : "=f"(f.x), "=f"(f.y) : "l"(v)); return f;
}
__device__ __forceinline__ float fsig(float x)  { return __fdividef(1.f, 1.f + __expf(-x)); }
__device__ __forceinline__ float ftanh(float x) { return 2.f * __fdividef(1.f, 1.f + __expf(-2.f * x)) - 1.f; }

#define CLU_ARRIVE() asm volatile("barrier.cluster.arrive.aligned;" ::: "memory")
#define CLU_WAIT()   asm volatile("barrier.cluster.wait.aligned;"   ::: "memory")
#define FULLM 0xffffffffu

// sum 64 partials of output o + REDUX argmax encode (tie -> smallest idx, exact)
__device__ __forceinline__ void logit_redux(const float* prow, float bo, int lane, int o,
                                            float& s, float& vmax, int& ia) {
    s = -1e30f;
    uint32_t enc = 0;
    if (lane < 8 && o < OUTD) {
        const float4* q = reinterpret_cast<const float4*>(prow);
        float t0 = 0.f, t1 = 0.f, t2 = 0.f, t3 = 0.f;
#pragma unroll
        for (int j = 0; j < 4; j++) {
            float4 a = q[4*j], b2 = q[4*j+1], c = q[4*j+2], d = q[4*j+3];
            t0 += (a.x + a.y) + (a.z + a.w);
            t1 += (b2.x + b2.y) + (b2.z + b2.w);
            t2 += (c.x + c.y) + (c.z + c.w);
            t3 += (d.x + d.y) + (d.z + d.w);
        }
        s = bo + ((t0 + t1) + (t2 + t3));
        // |s| small -> s+32 in (20,44): positive, monotone bit pattern
        enc = ((__float_as_uint(s + 32.0f) - 0x40000000u) << 3) | (uint32_t)(7 - o);
    }
    const uint32_t m = __reduce_max_sync(FULLM, enc);
    ia   = 7 - (int)(m & 7u);
    vmax = __uint_as_float((m >> 3) + 0x40000000u) - 32.0f;
}

// 2-CTA cluster per batch; all W_hh register-resident; barrier.cluster sync.
// R15 + 1-round plog producer (consumer sums 64 partials) + softmax-warp
// tf-step redux moved into the barrier window.
__global__ void __cluster_dims__(2, 1, 1) __launch_bounds__(TPB, 1)
lstm_decoder_kernel(const float* __restrict__ h0,
                    const float* __restrict__ c0,
                    const float* __restrict__ tonehot,   // (TLEN+1, 1, OUTD)
                    const void*  __restrict__ tfraw,     // tf_mask (dtype autodetect)
                    const float* __restrict__ W_ih,      // (4*HID, OUTD)
                    const float* __restrict__ W_hh,      // (4*HID, HID)
                    const float* __restrict__ b_ih,
                    const float* __restrict__ b_hh,
                    const float* __restrict__ W_out,     // (OUTD, HID)
                    const float* __restrict__ b_out,
                    float* __restrict__ out)             // [143360 lp | 1280 hT | 1280 cT]
{
    __shared__ __align__(16) float h_s[2][HID];       // full h per CTA, parity buffered
    __shared__ __align__(16) float plog_s[2][8][PSTR];// output-major: [o][64 partials]
    __shared__ int   tc_s[TLEN];                      // sign bit = tf (low bits tgt); 0 = greedy
    __shared__ int   tfmode_s;

    const int b    = blockIdx.x >> 1;    // batch
    const uint32_t rank = ctarank();     // 0 or 1
    const uint32_t peer = rank ^ 1u;
    const int tid  = threadIdx.x;
    const int lane = tid & 31;
    const int wid  = tid >> 5;           // 0..7
    const int ty   = tid & 3;            // gate type 0=i 1=f 2=g 3=o
    const int kl   = tid >> 2;           // local unit 0..63
    const int k    = (int)rank * KPC + kl;   // global hidden unit
    const int g    = ty * HID + k;           // gate row
    const int slot = (int)rank * 8 + wid;    // this warp's partial-column group
    const bool dosoft = (rank == 0 && wid == 7);

    // Full W_hh row g in registers: 64 packed u64 (128 regs)
    ull wp[HID / 2];
#pragma unroll
    for (int i = 0; i < HID / 4; i++) {
        float4 v = reinterpret_cast<const float4*>(W_hh + (size_t)g * HID)[i];
        wp[2*i]   = pk2(v.x, v.y);
        wp[2*i+1] = pk2(v.z, v.w);
    }
    const float biasg = b_ih[g] + b_hh[g];

    // W_ih row g (7 floats) in named registers -> SEL tree by xb bits
    const float wA = W_ih[g * OUTD + 0];
    const float wB = W_ih[g * OUTD + 1];
    const float wC = W_ih[g * OUTD + 2];
    const float wD = W_ih[g * OUTD + 3];
    const float wE = W_ih[g * OUTD + 4];
    const float wF = W_ih[g * OUTD + 5];
    const float wG = W_ih[g * OUTD + 6];

    const float wo1 = W_out[ty * HID + k];
    const float wo2 = (ty < 3) ? W_out[(ty + 4) * HID + k] : 0.f;

    float cval = c0[b * HID + k];

    // per-lane output bias (argmax/softmax path), register-resident
    const int o = lane & 7;
    const float bout_r = (o < OUTD) ? b_out[o] : 0.f;

    // producer store role: one shfl round leaves pair-sums; lanes with (lane&4)==0 store
    const int  uu   = lane >> 2;                 // unit-in-warp 0..7
    const int  pcol = slot * 4 + (uu >> 1);      // partial column 0..63
    const bool pst  = (lane & 4) == 0;

    // ---- init ----
    if (tid < HID) h_s[0][tid] = h0[b * HID + tid];
    for (int i = tid; i < 2 * 8 * PSTR; i += TPB) ((float*)plog_s)[i] = 0.f;
    if (tid == 0) {                                   // tf dtype autodetect
        const int* ip = (const int*)tfraw;
        int mode = 0;
        for (int i = 0; i < 512; i++) {
            int v = ip[i];
            if (v == 0x3f800000) { mode = 1; break; }
            if (v != 0 && v != 1) mode = 2;
        }
        tfmode_s = mode;
    }
    __syncthreads();
    {
        const int mode = tfmode_s;
        for (int s = tid; s < TLEN; s += TPB) {
            unsigned char tv;
            if (mode == 0)      tv = ((const int*)tfraw)[s] != 0;
            else if (mode == 1) tv = ((const float*)tfraw)[s] != 0.f;
            else                tv = ((const unsigned char*)tfraw)[s] != 0;
            const float* row = tonehot + (size_t)(s + 1) * OUTD;   // exactly one-hot
            int idx = 0; float best = row[0];
#pragma unroll
            for (int oo = 1; oo < OUTD; oo++) { if (row[oo] > best) { best = row[oo]; idx = oo; } }
            tc_s[s] = tv ? (int)(0x80000000u | (uint32_t)idx) : 0;   // 0 => greedy
        }
    }
    __syncthreads();
    CLU_ARRIVE(); CLU_WAIT();    // init visible cluster-wide

    // tcr carries tc_s[t-1] into iteration t; initial value = tf-encoded (OUTD-1) for x0
    int tcr = (int)(0x80000000u | (uint32_t)(OUTD - 1));

    // ================= main loop: one cluster.sync per step =================
#pragma unroll 2
    for (int t = 0; t < TLEN; t++) {
        const int p = t & 1;

        // ---- recurrent dot: all 128 cols, weights in regs, h broadcast-LDS ----
        ull acc0 = 0ull, acc1 = 0ull, acc2 = 0ull, acc3 = 0ull;
        const ulonglong2* hb = reinterpret_cast<const ulonglong2*>(h_s[p]);
#pragma unroll
        for (int i = 0; i < 16; i++) {
            ulonglong2 u = hb[2*i];
            ulonglong2 v = hb[2*i + 1];
            acc0 = fma2(u.x, wp[4*i],     acc0);
            acc1 = fma2(u.y, wp[4*i + 1], acc1);
            acc2 = fma2(v.x, wp[4*i + 2], acc2);
            acc3 = fma2(v.y, wp[4*i + 3], acc3);
        }

        // ---- next-input selection; argmax only on greedy steps (uniform branch) ----
        float slog = -1e30f, vmax = -1e30f;
        int xb;
        if (tcr < 0) {
            xb = tcr & 0xff;          // teacher-forced; softmax warp defers its redux to the window
        } else {
            int ia;
            logit_redux(&plog_s[p][o][0], bout_r, lane, o, slog, vmax, ia);
            xb = ia;
        }

        // ---- wih select (register SEL tree, no LDS on the xb chain) ----
        const float w01 = (xb & 1) ? wB : wA;
        const float w23 = (xb & 1) ? wD : wC;
        const float w45 = (xb & 1) ? wF : wE;
        const float wlo = (xb & 2) ? w23 : w01;
        const float whi = (xb & 2) ? wG  : w45;
        const float wihv = (xb & 4) ? whi : wlo;

        // ---- finish gate ----
        float2 f0 = unpk2(acc0), f1 = unpk2(acc1), f2 = unpk2(acc2), f3 = unpk2(acc3);
        float vb = ((f0.x + f0.y) + (f1.x + f1.y)) + ((f2.x + f2.y) + (f3.x + f3.y))
                 + biasg + wihv;
        vb = (ty == 2) ? ftanh(vb) : fsig(vb);

        // ---- quad butterfly: every lane gets (i,f,g,o) of its unit ----
        const float pb1 = __shfl_xor_sync(FULLM, vb, 1, 4);
        const float ev  = (ty & 1) ? pb1 : vb;
        const float od  = (ty & 1) ? vb  : pb1;
        const float ev2 = __shfl_xor_sync(FULLM, ev, 2, 4);
        const float od2 = __shfl_xor_sync(FULLM, od, 2, 4);
        const float gi = (ty & 2) ? ev2 : ev;
        const float gf = (ty & 2) ? od2 : od;
        const float gg = (ty & 2) ? ev  : ev2;
        const float go = (ty & 2) ? od  : od2;

        // ---- pointwise (redundant x4 per unit) ----
        cval = gf * cval + gi * gg;
        const float h2 = go * ftanh(cval);

        // ---- h publish: plain f32, peer first (start DSMEM flight early) ----
        if (ty == 0) {
            dst_f32(sm2u(&h_s[p ^ 1][k]), peer, h2);
            h_s[p ^ 1][k] = h2;
        }

        // ---- logit partials: ONE shfl round (pair-sum), 4 partials/output/warp ----
        float pl1 = h2 * wo1;
        float pl2 = h2 * wo2;
        pl1 += __shfl_xor_sync(FULLM, pl1, 4);
        pl2 += __shfl_xor_sync(FULLM, pl2, 4);
        if (pst) {
            const uint32_t a1 = sm2u(&plog_s[p ^ 1][ty][pcol]);
            const uint32_t a2 = sm2u(&plog_s[p ^ 1][ty + 4][pcol]);
            dst_f32(a1, peer, pl1);
            dst_f32(a2, peer, pl2);
            plog_s[p ^ 1][ty][pcol]     = pl1;
            plog_s[p ^ 1][ty + 4][pcol] = pl2;
        }

        // ---- cluster sync; tc prefetch + deferred redux + softmax in window ----
        CLU_ARRIVE();
        const int tcn = tc_s[t];          // tc for iteration t+1 (off critical path)
        if (t > 0 && dosoft) {
            if (tcr < 0) {                // tf step: redux deferred to here (race-safe:
                int ia_dummy;             // plog[p] rewrite is >=1 dot+chain after release)
                logit_redux(&plog_s[p][o][0], bout_r, lane, o, slog, vmax, ia_dummy);
            }
            float e = (lane < 8 && o < OUTD) ? __expf(slog - vmax) : 0.f;
#pragma unroll
            for (int d = 4; d >= 1; d >>= 1)
                e += __shfl_xor_sync(FULLM, e, d, 8);
            const float lse = vmax + __logf(e);
            if (lane < OUTD)
                out[(size_t)b * TLEN * OUTD + (size_t)(t - 1) * OUTD + lane] = slog - lse;
        }
        CLU_WAIT();
        tcr = tcn;
    }

    // ================= epilogue: logits for t = TLEN-1, final states =================
    {
        int ia_dummy;
        float s, v;
        logit_redux(&plog_s[0][o][0], bout_r, lane, o, s, v, ia_dummy);
        float e = (lane < 8 && o < OUTD) ? __expf(s - v) : 0.f;
#pragma unroll
        for (int d = 4; d >= 1; d >>= 1)
            e += __shfl_xor_sync(FULLM, e, d, 8);
        const float lse = v + __logf(e);
        if (dosoft && lane < OUTD)
            out[(size_t)b * TLEN * OUTD + (size_t)(TLEN - 1) * OUTD + lane] = s - lse;

        if (rank == 0) {
            for (int i = tid; i < HID; i += TPB)
                out[(size_t)BATCHN * TLEN * OUTD + b * HID + i] = h_s[0][i];
        }
        if (ty == 0)
            out[(size_t)BATCHN * TLEN * OUTD + BATCHN * HID + b * HID + k] = cval;
    }
    // keep cluster alive until all peer-targeted DSMEM traffic is consumed
    CLU_ARRIVE(); CLU_WAIT();
}

extern "C" void kernel_launch(void* const* d_in, const int* in_sizes, int n_in,
                              void* d_out, int out_size) {
    (void)in_sizes; (void)n_in; (void)out_size;
    const float* h0    = (const float*)d_in[0];
    const float* c0    = (const float*)d_in[1];
    const float* toh   = (const float*)d_in[2];
    const void*  tf    = d_in[3];
    const float* W_ih  = (const float*)d_in[4];
    const float* W_hh  = (const float*)d_in[5];
    const float* b_ih  = (const float*)d_in[6];
    const float* b_hh  = (const float*)d_in[7];
    const float* W_out = (const float*)d_in[8];
    const float* b_out = (const float*)d_in[9];
    float* out = (float*)d_out;

    lstm_decoder_kernel<<<2 * BATCHN, TPB>>>(h0, c0, toh, tf, W_ih, W_hh,
                                             b_ih, b_hh, W_out, b_out, out);
}

// round 17
// speedup vs baseline: 1.0976x; 1.0976x over previous
#include <cuda_runtime.h>
#include <cstdint>
#include <cstddef>

#define BATCHN 10
#define HID    128
#define OUTD   7
#define TLEN   2048
#define TPB    256      // 2 CTAs per batch; thread = one full gate row (ty,k)
#define KPC    64       // hidden units owned per CTA
#define PSTR   20       // plog row stride (floats): 80B, 16B-aligned, conflict-free

typedef unsigned long long ull;

__device__ __forceinline__ uint32_t sm2u(const void* p) {
    return (uint32_t)__cvta_generic_to_shared(const_cast<void*>(p));
}
__device__ __forceinline__ uint32_t ctarank() {
    uint32_t r; asm("mov.u32 %0, %%cluster_ctarank;" : "=r"(r)); return r;
}
__device__ __forceinline__ void dst_f32(uint32_t saddr, uint32_t rk, float v) {
    uint32_t ra;
    asm volatile("mapa.shared::cluster.u32 %0, %1, %2;" : "=r"(ra) : "r"(saddr), "r"(rk));
    asm volatile("st.shared::cluster.f32 [%0], %1;" :: "r"(ra), "f"(v) : "memory");
}
__device__ __forceinline__ ull fma2(ull a, ull b, ull c) {
    ull d; asm("fma.rn.f32x2 %0, %1, %2, %3;" : "=l"(d) : "l"(a), "l"(b), "l"(c)); return d;
}
__device__ __forceinline__ ull pk2(float lo, float hi) {
    ull r; asm("mov.b64 %0, {%1, %2};" : "=l"(r) : "f"(lo), "f"(hi)); return r;
}
__device__ __forceinline__ float2 unpk2(ull v) {
    float2 f; asm("mov.b64 {%0, %1}, %2;" : "=f"(f.x), "=f"(f.y) : "l"(v)); return f;
}
__device__ __forceinline__ float fsig(float x)  { return __fdividef(1.f, 1.f + __expf(-x)); }
__device__ __forceinline__ float ftanh(float x) { return 2.f * __fdividef(1.f, 1.f + __expf(-2.f * x)) - 1.f; }

#define CLU_ARRIVE() asm volatile("barrier.cluster.arrive.aligned;" ::: "memory")
#define CLU_WAIT()   asm volatile("barrier.cluster.wait.aligned;"   ::: "memory")
#define FULLM 0xffffffffu

// sum 16 warp-partials of output o + REDUX argmax encode (tie -> smallest idx, exact)
__device__ __forceinline__ void logit_redux(const float* prow, float bo, int lane, int o,
                                            float& s, float& vmax, int& ia) {
    s = -1e30f;
    uint32_t enc = 0;
    if (lane < 8 && o < OUTD) {
        const float4* q = reinterpret_cast<const float4*>(prow);
        float4 q0 = q[0], q1 = q[1], q2 = q[2], q3 = q[3];
        float t0 = (q0.x + q0.y) + (q0.z + q0.w);
        float t1 = (q1.x + q1.y) + (q1.z + q1.w);
        float t2 = (q2.x + q2.y) + (q2.z + q2.w);
        float t3 = (q3.x + q3.y) + (q3.z + q3.w);
        s = bo + ((t0 + t1) + (t2 + t3));
        // |s| small -> s+32 in (20,44): positive, monotone bit pattern
        enc = ((__float_as_uint(s + 32.0f) - 0x40000000u) << 3) | (uint32_t)(7 - o);
    }
    const uint32_t m = __reduce_max_sync(FULLM, enc);
    ia   = 7 - (int)(m & 7u);
    vmax = __uint_as_float((m >> 3) + 0x40000000u) - 32.0f;
}

// 2-CTA cluster per batch; all W_hh register-resident; barrier.cluster sync.
// R15 skeleton (3-round plog producer, 16-partial consumer) + softmax-warp
// tf-step redux deferred into the arrive->wait window.
__global__ void __cluster_dims__(2, 1, 1) __launch_bounds__(TPB, 1)
lstm_decoder_kernel(const float* __restrict__ h0,
                    const float* __restrict__ c0,
                    const float* __restrict__ tonehot,   // (TLEN+1, 1, OUTD)
                    const void*  __restrict__ tfraw,     // tf_mask (dtype autodetect)
                    const float* __restrict__ W_ih,      // (4*HID, OUTD)
                    const float* __restrict__ W_hh,      // (4*HID, HID)
                    const float* __restrict__ b_ih,
                    const float* __restrict__ b_hh,
                    const float* __restrict__ W_out,     // (OUTD, HID)
                    const float* __restrict__ b_out,
                    float* __restrict__ out)             // [143360 lp | 1280 hT | 1280 cT]
{
    __shared__ __align__(16) float h_s[2][HID];       // full h per CTA, parity buffered
    __shared__ __align__(16) float plog_s[2][8][PSTR];// output-major: [o][slot 0..15]
    __shared__ int   tc_s[TLEN];                      // sign bit = tf (low bits tgt); 0 = greedy
    __shared__ int   tfmode_s;

    const int b    = blockIdx.x >> 1;    // batch
    const uint32_t rank = ctarank();     // 0 or 1
    const uint32_t peer = rank ^ 1u;
    const int tid  = threadIdx.x;
    const int lane = tid & 31;
    const int wid  = tid >> 5;           // 0..7
    const int ty   = tid & 3;            // gate type 0=i 1=f 2=g 3=o
    const int kl   = tid >> 2;           // local unit 0..63
    const int k    = (int)rank * KPC + kl;   // global hidden unit
    const int g    = ty * HID + k;           // gate row
    const int slot = (int)rank * 8 + wid;    // this warp's plog column
    const bool dosoft = (rank == 0 && wid == 7);

    // Full W_hh row g in registers: 64 packed u64 (128 regs)
    ull wp[HID / 2];
#pragma unroll
    for (int i = 0; i < HID / 4; i++) {
        float4 v = reinterpret_cast<const float4*>(W_hh + (size_t)g * HID)[i];
        wp[2*i]   = pk2(v.x, v.y);
        wp[2*i+1] = pk2(v.z, v.w);
    }
    const float biasg = b_ih[g] + b_hh[g];

    // W_ih row g (7 floats) in named registers -> SEL tree by xb bits
    const float wA = W_ih[g * OUTD + 0];
    const float wB = W_ih[g * OUTD + 1];
    const float wC = W_ih[g * OUTD + 2];
    const float wD = W_ih[g * OUTD + 3];
    const float wE = W_ih[g * OUTD + 4];
    const float wF = W_ih[g * OUTD + 5];
    const float wG = W_ih[g * OUTD + 6];

    const float wo1 = W_out[ty * HID + k];
    const float wo2 = (ty < 3) ? W_out[(ty + 4) * HID + k] : 0.f;

    float cval = c0[b * HID + k];

    // per-lane output bias (argmax/softmax path), register-resident
    const int o = lane & 7;
    const float bout_r = (o < OUTD) ? b_out[o] : 0.f;

    // ---- init ----
    if (tid < HID) h_s[0][tid] = h0[b * HID + tid];
    for (int i = tid; i < 2 * 8 * PSTR; i += TPB) ((float*)plog_s)[i] = 0.f;
    if (tid == 0) {                                   // tf dtype autodetect
        const int* ip = (const int*)tfraw;
        int mode = 0;
        for (int i = 0; i < 512; i++) {
            int v = ip[i];
            if (v == 0x3f800000) { mode = 1; break; }
            if (v != 0 && v != 1) mode = 2;
        }
        tfmode_s = mode;
    }
    __syncthreads();
    {
        const int mode = tfmode_s;
        for (int s = tid; s < TLEN; s += TPB) {
            unsigned char tv;
            if (mode == 0)      tv = ((const int*)tfraw)[s] != 0;
            else if (mode == 1) tv = ((const float*)tfraw)[s] != 0.f;
            else                tv = ((const unsigned char*)tfraw)[s] != 0;
            const float* row = tonehot + (size_t)(s + 1) * OUTD;   // exactly one-hot
            int idx = 0; float best = row[0];
#pragma unroll
            for (int oo = 1; oo < OUTD; oo++) { if (row[oo] > best) { best = row[oo]; idx = oo; } }
            tc_s[s] = tv ? (int)(0x80000000u | (uint32_t)idx) : 0;   // 0 => greedy
        }
    }
    __syncthreads();
    CLU_ARRIVE(); CLU_WAIT();    // init visible cluster-wide

    // tcr carries tc_s[t-1] into iteration t; initial value = tf-encoded (OUTD-1) for x0
    int tcr = (int)(0x80000000u | (uint32_t)(OUTD - 1));

    // ================= main loop: one cluster.sync per step =================
#pragma unroll 2
    for (int t = 0; t < TLEN; t++) {
        const int p = t & 1;

        // ---- recurrent dot: all 128 cols, weights in regs, h broadcast-LDS ----
        ull acc0 = 0ull, acc1 = 0ull, acc2 = 0ull, acc3 = 0ull;
        const ulonglong2* hb = reinterpret_cast<const ulonglong2*>(h_s[p]);
#pragma unroll
        for (int i = 0; i < 16; i++) {
            ulonglong2 u = hb[2*i];
            ulonglong2 v = hb[2*i + 1];
            acc0 = fma2(u.x, wp[4*i],     acc0);
            acc1 = fma2(u.y, wp[4*i + 1], acc1);
            acc2 = fma2(v.x, wp[4*i + 2], acc2);
            acc3 = fma2(v.y, wp[4*i + 3], acc3);
        }

        // ---- next-input selection; argmax only on greedy steps (uniform branch) ----
        float slog = -1e30f, vmax = -1e30f;
        int xb;
        if (tcr < 0) {
            xb = tcr & 0xff;      // teacher-forced; softmax warp defers redux to the window
        } else {
            int ia;
            logit_redux(&plog_s[p][o][0], bout_r, lane, o, slog, vmax, ia);
            xb = ia;
        }

        // ---- wih select (register SEL tree, no LDS on the xb chain) ----
        const float w01 = (xb & 1) ? wB : wA;
        const float w23 = (xb & 1) ? wD : wC;
        const float w45 = (xb & 1) ? wF : wE;
        const float wlo = (xb & 2) ? w23 : w01;
        const float whi = (xb & 2) ? wG  : w45;
        const float wihv = (xb & 4) ? whi : wlo;

        // ---- finish gate ----
        float2 f0 = unpk2(acc0), f1 = unpk2(acc1), f2 = unpk2(acc2), f3 = unpk2(acc3);
        float vb = ((f0.x + f0.y) + (f1.x + f1.y)) + ((f2.x + f2.y) + (f3.x + f3.y))
                 + biasg + wihv;
        vb = (ty == 2) ? ftanh(vb) : fsig(vb);

        // ---- quad butterfly: every lane gets (i,f,g,o) of its unit ----
        const float pb1 = __shfl_xor_sync(FULLM, vb, 1, 4);
        const float ev  = (ty & 1) ? pb1 : vb;
        const float od  = (ty & 1) ? vb  : pb1;
        const float ev2 = __shfl_xor_sync(FULLM, ev, 2, 4);
        const float od2 = __shfl_xor_sync(FULLM, od, 2, 4);
        const float gi = (ty & 2) ? ev2 : ev;
        const float gf = (ty & 2) ? od2 : od;
        const float gg = (ty & 2) ? ev  : ev2;
        const float go = (ty & 2) ? od  : od2;

        // ---- pointwise (redundant x4 per unit) ----
        cval = gf * cval + gi * gg;
        const float h2 = go * ftanh(cval);

        // ---- h publish: plain f32, peer first (start DSMEM flight early) ----
        if (ty == 0) {
            dst_f32(sm2u(&h_s[p ^ 1][k]), peer, h2);
            h_s[p ^ 1][k] = h2;
        }

        // ---- logit partials over the warp's 8 units; output-major publish ----
        float pl1 = h2 * wo1;
        float pl2 = h2 * wo2;
#pragma unroll
        for (int d = 4; d <= 16; d <<= 1) {
            pl1 += __shfl_xor_sync(FULLM, pl1, d);
            pl2 += __shfl_xor_sync(FULLM, pl2, d);
        }
        if (lane < 4) {
            const uint32_t a1 = sm2u(&plog_s[p ^ 1][ty][slot]);
            const uint32_t a2 = sm2u(&plog_s[p ^ 1][ty + 4][slot]);
            dst_f32(a1, peer, pl1);
            dst_f32(a2, peer, pl2);
            plog_s[p ^ 1][ty][slot]     = pl1;
            plog_s[p ^ 1][ty + 4][slot] = pl2;
        }

        // ---- cluster sync; tc prefetch + deferred tf-redux + softmax in window ----
        CLU_ARRIVE();
        const int tcn = tc_s[t];          // tc for iteration t+1 (off critical path)
        if (t > 0 && dosoft) {
            if (tcr < 0) {                // tf step: redux deferred here (race-safe:
                int ia_dummy;             // plog[p] rewrite >= release + dot + chain)
                logit_redux(&plog_s[p][o][0], bout_r, lane, o, slog, vmax, ia_dummy);
            }
            float e = (lane < 8 && o < OUTD) ? __expf(slog - vmax) : 0.f;
#pragma unroll
            for (int d = 4; d >= 1; d >>= 1)
                e += __shfl_xor_sync(FULLM, e, d, 8);
            const float lse = vmax + __logf(e);
            if (lane < OUTD)
                out[(size_t)b * TLEN * OUTD + (size_t)(t - 1) * OUTD + lane] = slog - lse;
        }
        CLU_WAIT();
        tcr = tcn;
    }

    // ================= epilogue: logits for t = TLEN-1, final states =================
    {
        int ia_dummy;
        float s, v;
        logit_redux(&plog_s[0][o][0], bout_r, lane, o, s, v, ia_dummy);
        float e = (lane < 8 && o < OUTD) ? __expf(s - v) : 0.f;
#pragma unroll
        for (int d = 4; d >= 1; d >>= 1)
            e += __shfl_xor_sync(FULLM, e, d, 8);
        const float lse = v + __logf(e);
        if (dosoft && lane < OUTD)
            out[(size_t)b * TLEN * OUTD + (size_t)(TLEN - 1) * OUTD + lane] = s - lse;

        if (rank == 0) {
            for (int i = tid; i < HID; i += TPB)
                out[(size_t)BATCHN * TLEN * OUTD + b * HID + i] = h_s[0][i];
        }
        if (ty == 0)
            out[(size_t)BATCHN * TLEN * OUTD + BATCHN * HID + b * HID + k] = cval;
    }
    // keep cluster alive until all peer-targeted DSMEM traffic is consumed
    CLU_ARRIVE(); CLU_WAIT();
}

extern "C" void kernel_launch(void* const* d_in, const int* in_sizes, int n_in,
                              void* d_out, int out_size) {
    (void)in_sizes; (void)n_in; (void)out_size;
    const float* h0    = (const float*)d_in[0];
    const float* c0    = (const float*)d_in[1];
    const float* toh   = (const float*)d_in[2];
    const void*  tf    = d_in[3];
    const float* W_ih  = (const float*)d_in[4];
    const float* W_hh  = (const float*)d_in[5];
    const float* b_ih  = (const float*)d_in[6];
    const float* b_hh  = (const float*)d_in[7];
    const float* W_out = (const float*)d_in[8];
    const float* b_out = (const float*)d_in[9];
    float* out = (float*)d_out;

    lstm_decoder_kernel<<<2 * BATCHN, TPB>>>(h0, c0, toh, tf, W_ih, W_hh,
                                             b_ih, b_hh, W_out, b_out, out);
}